// round 8
// baseline (speedup 1.0000x reference)
#include <cuda_runtime.h>
#include <cuda_fp16.h>

// ---------------------------------------------------------------------------
// SlabAttention: B=16, N=4096, C=384, H=12, hd=32, BH=192
// Round 6: BK=64 GEMMs; kv_kernel 4x4 outer-product blocking; merged zeroing.
// ---------------------------------------------------------------------------

#define BATCH   16
#define NTOK    4096
#define CDIM    384
#define HEADS   12
#define HD      32
#define BH_TOT  (BATCH*HEADS)      // 192
#define M_TOT   (BATCH*NTOK)       // 65536
#define EPS     1e-6f

#define BK   64
#define LDH  72    // halfs per smem row: 64 + 8 pad (144B = 9 16B-cols; 9 mod 8 = 1
                   // -> 8 consecutive rows hit 8 distinct 16B columns: conflict-free)

// scratch (device globals; allocation-free rule)
__device__ alignas(256) __half g_xh   [(size_t)M_TOT * CDIM];
__device__ alignas(256) __half g_wqkv [(size_t)3 * CDIM * CDIM];
__device__ alignas(256) __half g_wproj[(size_t)CDIM * CDIM];
__device__ alignas(256) __half g_qh   [(size_t)BH_TOT * NTOK * HD];
__device__ alignas(256) __half g_kh   [(size_t)BH_TOT * NTOK * HD];
__device__ alignas(256) __half g_vh   [(size_t)BH_TOT * NTOK * HD];
__device__ alignas(256) __half g_preh [(size_t)M_TOT * CDIM];
__device__ float  g_ksum [BH_TOT * HD];
__device__ float  g_kv   [BH_TOT * HD * HD];

__device__ __forceinline__ void mma_f16(float* c, const unsigned* A, const unsigned* B) {
    asm volatile(
        "mma.sync.aligned.m16n8k16.row.col.f32.f16.f16.f32 "
        "{%0,%1,%2,%3},{%4,%5,%6,%7},{%8,%9},{%0,%1,%2,%3};\n"
        : "+f"(c[0]), "+f"(c[1]), "+f"(c[2]), "+f"(c[3])
        : "r"(A[0]), "r"(A[1]), "r"(A[2]), "r"(A[3]), "r"(B[0]), "r"(B[1]));
}

__device__ __forceinline__ void ldsm_x4(unsigned* r, unsigned addr) {
    asm volatile("ldmatrix.sync.aligned.m8n8.x4.shared.b16 {%0,%1,%2,%3}, [%4];\n"
        : "=r"(r[0]), "=r"(r[1]), "=r"(r[2]), "=r"(r[3]) : "r"(addr));
}

__device__ __forceinline__ void cp16h(__half* smem, const __half* g) {
    unsigned saddr = (unsigned)__cvta_generic_to_shared(smem);
    asm volatile("cp.async.cg.shared.global [%0], [%1], 16;\n" :: "r"(saddr), "l"(g));
}
#define CP_COMMIT  asm volatile("cp.async.commit_group;\n")
#define CP_WAIT(n) asm volatile("cp.async.wait_group %0;\n" :: "n"(n))

// smem: 2 stages x (A 128 rows + B 128 rows) x LDH halfs x 2B = 73728
#define GEMM_SMEM (4 * 128 * LDH * 2)

// ---------------------------------------------------------------------------
// Conversion kernels (zeroing of kv/ksum folded into cvt_w_zero)
// ---------------------------------------------------------------------------
__global__ __launch_bounds__(256) void cvt_x(const float4* __restrict__ x)
{
    const size_t i = (size_t)blockIdx.x * 256 + threadIdx.x;
    float4 v = x[i];
    *(__half2*)&g_xh[i * 4]     = __floats2half2_rn(v.x, v.y);
    *(__half2*)&g_xh[i * 4 + 2] = __floats2half2_rn(v.z, v.w);
}

__global__ __launch_bounds__(256) void cvt_w_zero(const float* __restrict__ qkv_w,
                                                  const float* __restrict__ proj_w)
{
    const int i = blockIdx.x * 256 + threadIdx.x;            // < 589824
    if (i < 3 * CDIM * CDIM) g_wqkv[i] = __float2half_rn(qkv_w[i]);
    else g_wproj[i - 3 * CDIM * CDIM] = __float2half_rn(proj_w[i - 3 * CDIM * CDIM]);
    if (i < BH_TOT * HD * HD) g_kv[i] = 0.f;
    if (i < BH_TOT * HD)      g_ksum[i] = 0.f;
}

// ---------------------------------------------------------------------------
// GEMM core: BM=128, BN=128, BK=64, 256 thr (8 warps 2Mx4N), warp tile 64x32.
// ---------------------------------------------------------------------------
#define GEMM_PROLOGUE(GA, GB)                                                   \
    extern __shared__ __half smh[];                                             \
    __half* As[2] = { smh,             smh + 128 * LDH };                       \
    __half* Bs[2] = { smh + 2*128*LDH, smh + 3*128*LDH };                       \
    const int tid  = threadIdx.x;                                               \
    const int mB   = blockIdx.y * 128;                                          \
    const int jB   = blockIdx.x * 128;                                          \
    const int lane = tid & 31;                                                  \
    const int warp = tid >> 5;                                                  \
    const int g    = lane >> 2;                                                 \
    const int t    = lane & 3;                                                  \
    const int wM   = (warp & 1) * 64;                                           \
    const int wN   = (warp >> 1) * 32;                                          \
    const int li   = lane & 7;                                                  \
    const int seg  = lane >> 3;                                                 \
    int aoff[4], boff[2];                                                       \
    _Pragma("unroll")                                                           \
    for (int mt = 0; mt < 4; mt++)                                              \
        aoff[mt] = (wM + mt*16 + li + (seg & 1)*8) * LDH + (seg >> 1)*8;        \
    _Pragma("unroll")                                                           \
    for (int np = 0; np < 2; np++)                                              \
        boff[np] = (wN + np*16 + li + (seg >> 1)*8) * LDH + (seg & 1)*8;        \
    float acc[4][4][4];                                                         \
    _Pragma("unroll")                                                           \
    for (int i = 0; i < 4; i++)                                                 \
        _Pragma("unroll")                                                       \
        for (int j = 0; j < 4; j++)                                             \
            _Pragma("unroll")                                                   \
            for (int l = 0; l < 4; l++) acc[i][j][l] = 0.f;

// BK=64 stage: thread -> row = tid>>1 (0..127), 4 consecutive 16B chunks.
#define LOAD_STAGE(s, k0, GA, GB)                                               \
    {                                                                           \
        const int row = tid >> 1;                                               \
        const int cb  = (tid & 1) * 4;                                          \
        _Pragma("unroll")                                                       \
        for (int i = 0; i < 4; i++) {                                           \
            cp16h(&As[s][row*LDH + (cb + i)*8],                                 \
                  &GA[(size_t)(mB + row)*CDIM + (k0) + (cb + i)*8]);            \
            cp16h(&Bs[s][row*LDH + (cb + i)*8],                                 \
                  &GB[(size_t)(jB + row)*CDIM + (k0) + (cb + i)*8]);            \
        }                                                                       \
        CP_COMMIT;                                                              \
    }

#define GEMM_MAINLOOP(GA, GB)                                                   \
    LOAD_STAGE(0, 0, GA, GB);                                                   \
    int s = 0;                                                                  \
    for (int k0 = 0; k0 < CDIM; k0 += BK) {                                     \
        if (k0 + BK < CDIM) { LOAD_STAGE(s ^ 1, k0 + BK, GA, GB); CP_WAIT(1); } \
        else                { CP_WAIT(0); }                                     \
        __syncthreads();                                                        \
        const unsigned uA = (unsigned)__cvta_generic_to_shared(As[s]);          \
        const unsigned uB = (unsigned)__cvta_generic_to_shared(Bs[s]);          \
        _Pragma("unroll")                                                       \
        for (int ks = 0; ks < BK; ks += 16) {                                   \
            unsigned a[4][4], bb[2][4];                                         \
            _Pragma("unroll")                                                   \
            for (int mt = 0; mt < 4; mt++)                                      \
                ldsm_x4(a[mt], uA + 2u * (unsigned)(aoff[mt] + ks));            \
            _Pragma("unroll")                                                   \
            for (int np = 0; np < 2; np++)                                      \
                ldsm_x4(bb[np], uB + 2u * (unsigned)(boff[np] + ks));           \
            _Pragma("unroll")                                                   \
            for (int mt = 0; mt < 4; mt++)                                      \
                _Pragma("unroll")                                               \
                for (int nt = 0; nt < 4; nt++)                                  \
                    mma_f16(acc[mt][nt], a[mt], &bb[nt >> 1][(nt & 1) * 2]);    \
        }                                                                       \
        __syncthreads();                                                        \
        s ^= 1;                                                                 \
    }

// ---------------------------------------------------------------------------
// Kernel 1: qkv GEMM (M=65536, Nout=1152, K=384) + fused epilogue.
// ---------------------------------------------------------------------------
__global__ __launch_bounds__(256) void qkv_gemm(const float* __restrict__ pos)
{
    GEMM_PROLOGUE(g_xh, g_wqkv)
    GEMM_MAINLOOP(g_xh, g_wqkv)

    const int part = jB / CDIM;                 // 0=q, 1=k, 2=v (uniform/block)
#pragma unroll
    for (int mt = 0; mt < 4; mt++) {
#pragma unroll
        for (int nt = 0; nt < 4; nt++) {
            const int j = jB + wN + nt * 8 + 2 * t;
            const int c = j - part * CDIM;
            const int h = c >> 5;
            const int d = c & 31;
#pragma unroll
            for (int hh = 0; hh < 2; hh++) {
                const int m = mB + wM + mt * 16 + g + hh * 8;
                const int b_ = m >> 12;
                const int n  = m & 4095;
                float v0 = acc[mt][nt][hh * 2 + 0];
                float v1 = acc[mt][nt][hh * 2 + 1];
                const size_t o = (((size_t)(b_ * HEADS + h)) * NTOK + n) * HD + d;
                if (part == 0) {
                    *(__half2*)&g_qh[o] =
                        __floats2half2_rn(fmaxf(v0, 0.f), fmaxf(v1, 0.f));
                } else if (part == 1) {
                    v0 = fmaxf(v0 + pos[(size_t)n * CDIM + c],     0.f);
                    v1 = fmaxf(v1 + pos[(size_t)n * CDIM + c + 1], 0.f);
                    *(__half2*)&g_kh[o] = __floats2half2_rn(v0, v1);
                } else {
                    *(__half2*)&g_vh[o] = __floats2half2_rn(v0, v1);
                }
            }
        }
    }
}

// ---------------------------------------------------------------------------
// Kernel 2: kv[bh,c,d] += sum_{chunk} k*v ; ksum fused. grid (192, 8).
// 4 row-groups x (8 c-quads x 8 d-quads); 4x4 outer product per thread:
// 2 LDS.128 (both broadcast-class) feed 16 FFMA per row.
// ---------------------------------------------------------------------------
__global__ __launch_bounds__(256) void kv_kernel()
{
    const int bh  = blockIdx.x;
    const int j0s = blockIdx.y * 512;
    const int tid = threadIdx.x;
    const int g   = tid >> 6;           // row group 0..3
    const int cq  = (tid >> 3) & 7;     // c quad 0..7
    const int dq  = tid & 7;            // d quad 0..7
    const int d32 = tid & 31;
    const int gr8 = tid >> 5;
    __shared__ float sk[64 * 32];
    __shared__ float sv[64 * 32];
    __shared__ float sacc[4][1024];
    __shared__ float sred[256];
    const size_t base = (size_t)bh * NTOK * HD;
    float acc[4][4];
#pragma unroll
    for (int i = 0; i < 4; i++)
#pragma unroll
        for (int j = 0; j < 4; j++) acc[i][j] = 0.f;
    float ksacc = 0.f;

    for (int j0 = j0s; j0 < j0s + 512; j0 += 64) {
        for (int i = tid; i < 512; i += 256) {
            const size_t gi = base + (size_t)j0 * HD + i * 4;
            float2 k01 = __half22float2(*(const __half2*)&g_kh[gi]);
            float2 k23 = __half22float2(*(const __half2*)&g_kh[gi + 2]);
            float2 v01 = __half22float2(*(const __half2*)&g_vh[gi]);
            float2 v23 = __half22float2(*(const __half2*)&g_vh[gi + 2]);
            *(float4*)&sk[i * 4] = make_float4(k01.x, k01.y, k23.x, k23.y);
            *(float4*)&sv[i * 4] = make_float4(v01.x, v01.y, v23.x, v23.y);
        }
        __syncthreads();
#pragma unroll
        for (int rr = 0; rr < 16; rr++) {
            const int r = rr * 4 + g;
            float4 kk = *(const float4*)&sk[r * 32 + cq * 4];
            float4 vv = *(const float4*)&sv[r * 32 + dq * 4];
            acc[0][0] += kk.x * vv.x; acc[0][1] += kk.x * vv.y;
            acc[0][2] += kk.x * vv.z; acc[0][3] += kk.x * vv.w;
            acc[1][0] += kk.y * vv.x; acc[1][1] += kk.y * vv.y;
            acc[1][2] += kk.y * vv.z; acc[1][3] += kk.y * vv.w;
            acc[2][0] += kk.z * vv.x; acc[2][1] += kk.z * vv.y;
            acc[2][2] += kk.z * vv.z; acc[2][3] += kk.z * vv.w;
            acc[3][0] += kk.w * vv.x; acc[3][1] += kk.w * vv.y;
            acc[3][2] += kk.w * vv.z; acc[3][3] += kk.w * vv.w;
        }
#pragma unroll
        for (int r8 = 0; r8 < 8; r8++) ksacc += sk[(gr8 + r8 * 8) * 32 + d32];
        __syncthreads();
    }

    // group partials -> smem, cross-group sum, one atomicAdd per output
#pragma unroll
    for (int i = 0; i < 4; i++)
        *(float4*)&sacc[g][(cq * 4 + i) * 32 + dq * 4] =
            make_float4(acc[i][0], acc[i][1], acc[i][2], acc[i][3]);
    sred[tid] = ksacc;
    __syncthreads();
    {
        float4 a0 = *(const float4*)&sacc[0][tid * 4];
        float4 a1 = *(const float4*)&sacc[1][tid * 4];
        float4 a2 = *(const float4*)&sacc[2][tid * 4];
        float4 a3 = *(const float4*)&sacc[3][tid * 4];
        atomicAdd(&g_kv[bh * 1024 + tid * 4 + 0], a0.x + a1.x + a2.x + a3.x);
        atomicAdd(&g_kv[bh * 1024 + tid * 4 + 1], a0.y + a1.y + a2.y + a3.y);
        atomicAdd(&g_kv[bh * 1024 + tid * 4 + 2], a0.z + a1.z + a2.z + a3.z);
        atomicAdd(&g_kv[bh * 1024 + tid * 4 + 3], a0.w + a1.w + a2.w + a3.w);
    }
    if (gr8 == 0) {
        float ssum = 0.f;
#pragma unroll
        for (int gg = 0; gg < 8; gg++) ssum += sred[gg * 32 + d32];
        atomicAdd(&g_ksum[bh * HD + d32], ssum);
    }
}

// ---------------------------------------------------------------------------
// Kernel 4: attn_out (unchanged from round 5).
// ---------------------------------------------------------------------------
#define SV_ROW (68 * 32)
#define ATTN_SMEM (5*SV_ROW*2 + (2048 + 1024 + 800 + 32) * 4)

__global__ __launch_bounds__(256, 4) void attn_out(const float* __restrict__ dwc_w,
                                                   const float* __restrict__ dwc_b)
{
    extern __shared__ float sm[];
    __half* svh = (__half*)sm;                  // 5 * SV_ROW halfs
    float* sq  = sm + (5 * SV_ROW * 2) / 4;     // 2048 floats
    float* skv = sq + 2048;                     // 1024
    float* sw  = skv + 1024;                    // 800
    float* sks = sw + 800;                      // 32

    const int y  = blockIdx.x;
    const int bh = blockIdx.y;
    const int tid = threadIdx.x;
    const int d  = tid & 31;
    const int gr = tid >> 5;
    const int x0 = gr * 8;
    const size_t base = (size_t)bh * NTOK * HD;

    for (int i = tid; i < 5 * 4 * 32; i += 256) {
        const int row = i >> 7;
        const int rem = i & 127;
        const int col = rem >> 5;
        const int dd  = rem & 31;
        const int xc  = (col < 2) ? col : (64 + col);
        svh[row * SV_ROW + xc * 32 + dd] = __float2half(0.f);
    }
#pragma unroll
    for (int ky = 0; ky < 5; ky++) {
        const int yy = y + ky - 2;
        for (int c = tid; c < 512; c += 256) {
            const int x = c >> 3, dq = (c & 7) * 4;
            uint2 val = make_uint2(0u, 0u);
            if ((unsigned)yy < 64u)
                val = *(const uint2*)&g_vh[base + ((size_t)(yy * 64 + x)) * HD + dq];
            *(uint2*)&svh[ky * SV_ROW + (x + 2) * 32 + dq] = val;
        }
    }
    for (int c = tid; c < 512; c += 256) {
        const int x = c >> 3, dq = (c & 7) * 4;
        const size_t gi = base + ((size_t)(y * 64 + x)) * HD + dq;
        float2 a = __half22float2(*(const __half2*)&g_qh[gi]);
        float2 bq = __half22float2(*(const __half2*)&g_qh[gi + 2]);
        *(float4*)&sq[x * 32 + dq] = make_float4(a.x, a.y, bq.x, bq.y);
    }
    *(float4*)&skv[tid * 4] = *(const float4*)&g_kv[bh * 1024 + tid * 4];
    for (int i = tid; i < 800; i += 256) sw[i] = dwc_w[i];
    if (tid < 32) sks[tid] = g_ksum[bh * HD + tid];
    __syncthreads();

    float rkv[32];
#pragma unroll
    for (int c = 0; c < 32; c++) rkv[c] = skv[c * 32 + d];
    const float rks = sks[d];
    const float rb  = dwc_b[d];

    float acc[8];
#pragma unroll
    for (int xi = 0; xi < 8; xi++) acc[xi] = rb;
#pragma unroll
    for (int ky = 0; ky < 5; ky++) {
        float w[12];
#pragma unroll
        for (int j = 0; j < 12; j++)
            w[j] = __half2float(svh[ky * SV_ROW + (x0 + j) * 32 + d]);
#pragma unroll
        for (int kx = 0; kx < 5; kx++) {
            const float cf = sw[d * 25 + ky * 5 + kx];
#pragma unroll
            for (int xi = 0; xi < 8; xi++) acc[xi] += cf * w[xi + kx];
        }
    }

    const int b_ = bh / HEADS, h = bh % HEADS;
#pragma unroll
    for (int xi = 0; xi < 8; xi++) {
        const int tok = x0 + xi;
        float o = 0.f;
#pragma unroll
        for (int c = 0; c < 32; c++) o += sq[tok * 32 + c] * rkv[c];
        float p = sq[tok * 32 + d] * rks;
#pragma unroll
        for (int off = 16; off; off >>= 1) p += __shfl_xor_sync(0xffffffffu, p, off);
        const float z = 1.f / (p + EPS);
        const int n = y * 64 + tok;
        g_preh[((size_t)(b_ * NTOK + n)) * CDIM + h * HD + d] =
            __float2half_rn(o * z + acc[xi]);
    }
}

// ---------------------------------------------------------------------------
// Kernel 5: proj GEMM (M=65536, Nout=384, K=384) + bias -> out (fp32).
// ---------------------------------------------------------------------------
__global__ __launch_bounds__(256) void proj_gemm(const float* __restrict__ bias,
                                                 float* __restrict__ out)
{
    GEMM_PROLOGUE(g_preh, g_wproj)
    GEMM_MAINLOOP(g_preh, g_wproj)

#pragma unroll
    for (int mt = 0; mt < 4; mt++) {
#pragma unroll
        for (int nt = 0; nt < 4; nt++) {
            const int j = jB + wN + nt * 8 + 2 * t;
            const float b0 = bias[j], b1 = bias[j + 1];
#pragma unroll
            for (int hh = 0; hh < 2; hh++) {
                const int m = mB + wM + mt * 16 + g + hh * 8;
                *(float2*)&out[(size_t)m * CDIM + j] =
                    make_float2(acc[mt][nt][hh * 2 + 0] + b0,
                                acc[mt][nt][hh * 2 + 1] + b1);
            }
        }
    }
}

// ---------------------------------------------------------------------------
extern "C" void kernel_launch(void* const* d_in, const int* in_sizes, int n_in,
                              void* d_out, int out_size)
{
    const float* x      = (const float*)d_in[0];
    const float* qkv_w  = (const float*)d_in[1];
    const float* pos    = (const float*)d_in[2];
    const float* dwc_w  = (const float*)d_in[3];
    const float* dwc_b  = (const float*)d_in[4];
    const float* proj_w = (const float*)d_in[5];
    const float* proj_b = (const float*)d_in[6];
    float* out = (float*)d_out;

    cudaFuncSetAttribute(qkv_gemm,  cudaFuncAttributeMaxDynamicSharedMemorySize, GEMM_SMEM);
    cudaFuncSetAttribute(proj_gemm, cudaFuncAttributeMaxDynamicSharedMemorySize, GEMM_SMEM);
    cudaFuncSetAttribute(attn_out,  cudaFuncAttributeMaxDynamicSharedMemorySize, ATTN_SMEM);

    cvt_x<<<24576, 256>>>((const float4*)x);
    cvt_w_zero<<<2304, 256>>>(qkv_w, proj_w);

    dim3 g1(9, M_TOT / 128);              // 1152/128 x 512
    qkv_gemm<<<g1, 256, GEMM_SMEM>>>(pos);

    dim3 g3(BH_TOT, 8);
    kv_kernel<<<g3, 256>>>();

    dim3 g4(64, BH_TOT);
    attn_out<<<g4, 256, ATTN_SMEM>>>(dwc_w, dwc_b);

    dim3 g5(3, M_TOT / 128);              // 384/128 x 512
    proj_gemm<<<g5, 256, GEMM_SMEM>>>(proj_b, out);
}

// round 10
// speedup vs baseline: 1.1690x; 1.1690x over previous
#include <cuda_runtime.h>
#include <cuda_fp16.h>

// ---------------------------------------------------------------------------
// SlabAttention: B=16, N=4096, C=384, H=12, hd=32, BH=192
// Round 8: GEMMs back to BK=32/LDH=40 (round-5 geometry) + 3-stage cp.async;
// keep round-6 kv_kernel (4x4 outer product) and merged zeroing.
// ---------------------------------------------------------------------------

#define BATCH   16
#define NTOK    4096
#define CDIM    384
#define HEADS   12
#define HD      32
#define BH_TOT  (BATCH*HEADS)      // 192
#define M_TOT   (BATCH*NTOK)       // 65536
#define EPS     1e-6f

#define BK   32
#define LDH  40    // halfs per smem row: 32 + 8 pad (80B stride)
                   // ldmatrix phase: chunk = (row*5 + col/8) mod 8, 5 coprime 8
                   // -> 8 consecutive rows hit 8 distinct 16B columns: conflict-free

// scratch (device globals; allocation-free rule)
__device__ alignas(256) __half g_xh   [(size_t)M_TOT * CDIM];
__device__ alignas(256) __half g_wqkv [(size_t)3 * CDIM * CDIM];
__device__ alignas(256) __half g_wproj[(size_t)CDIM * CDIM];
__device__ alignas(256) __half g_qh   [(size_t)BH_TOT * NTOK * HD];
__device__ alignas(256) __half g_kh   [(size_t)BH_TOT * NTOK * HD];
__device__ alignas(256) __half g_vh   [(size_t)BH_TOT * NTOK * HD];
__device__ alignas(256) __half g_preh [(size_t)M_TOT * CDIM];
__device__ float  g_ksum [BH_TOT * HD];
__device__ float  g_kv   [BH_TOT * HD * HD];

__device__ __forceinline__ void mma_f16(float* c, const unsigned* A, const unsigned* B) {
    asm volatile(
        "mma.sync.aligned.m16n8k16.row.col.f32.f16.f16.f32 "
        "{%0,%1,%2,%3},{%4,%5,%6,%7},{%8,%9},{%0,%1,%2,%3};\n"
        : "+f"(c[0]), "+f"(c[1]), "+f"(c[2]), "+f"(c[3])
        : "r"(A[0]), "r"(A[1]), "r"(A[2]), "r"(A[3]), "r"(B[0]), "r"(B[1]));
}

__device__ __forceinline__ void ldsm_x4(unsigned* r, unsigned addr) {
    asm volatile("ldmatrix.sync.aligned.m8n8.x4.shared.b16 {%0,%1,%2,%3}, [%4];\n"
        : "=r"(r[0]), "=r"(r[1]), "=r"(r[2]), "=r"(r[3]) : "r"(addr));
}

__device__ __forceinline__ void cp16h(__half* smem, const __half* g) {
    unsigned saddr = (unsigned)__cvta_generic_to_shared(smem);
    asm volatile("cp.async.cg.shared.global [%0], [%1], 16;\n" :: "r"(saddr), "l"(g));
}
#define CP_COMMIT  asm volatile("cp.async.commit_group;\n")
#define CP_WAIT(n) asm volatile("cp.async.wait_group %0;\n" :: "n"(n))

// smem: 3 stages x (A 128 + B 128 rows) x LDH halfs x 2B = 61440
#define GEMM_SMEM (6 * 128 * LDH * 2)

// ---------------------------------------------------------------------------
// Conversion kernels (zeroing of kv/ksum folded in)
// ---------------------------------------------------------------------------
__global__ __launch_bounds__(256) void cvt_x(const float4* __restrict__ x)
{
    const size_t i = (size_t)blockIdx.x * 256 + threadIdx.x;
    float4 v = x[i];
    *(__half2*)&g_xh[i * 4]     = __floats2half2_rn(v.x, v.y);
    *(__half2*)&g_xh[i * 4 + 2] = __floats2half2_rn(v.z, v.w);
}

__global__ __launch_bounds__(256) void cvt_w_zero(const float* __restrict__ qkv_w,
                                                  const float* __restrict__ proj_w)
{
    const int i = blockIdx.x * 256 + threadIdx.x;            // < 589824
    if (i < 3 * CDIM * CDIM) g_wqkv[i] = __float2half_rn(qkv_w[i]);
    else g_wproj[i - 3 * CDIM * CDIM] = __float2half_rn(proj_w[i - 3 * CDIM * CDIM]);
    if (i < BH_TOT * HD * HD) g_kv[i] = 0.f;
    if (i < BH_TOT * HD)      g_ksum[i] = 0.f;
}

// ---------------------------------------------------------------------------
// GEMM core: BM=128, BN=128, BK=32, 256 thr (8 warps 2Mx4N), warp tile 64x32.
// 3-stage cp.async pipeline (2 prefetches in flight).
// ---------------------------------------------------------------------------
#define GEMM_PROLOGUE(GA, GB)                                                   \
    extern __shared__ __half smh[];                                             \
    __half* As[3] = { smh, smh + 128*LDH, smh + 2*128*LDH };                    \
    __half* Bs[3] = { smh + 3*128*LDH, smh + 4*128*LDH, smh + 5*128*LDH };      \
    const int tid  = threadIdx.x;                                               \
    const int mB   = blockIdx.y * 128;                                          \
    const int jB   = blockIdx.x * 128;                                          \
    const int lane = tid & 31;                                                  \
    const int warp = tid >> 5;                                                  \
    const int g    = lane >> 2;                                                 \
    const int t    = lane & 3;                                                  \
    const int wM   = (warp & 1) * 64;                                           \
    const int wN   = (warp >> 1) * 32;                                          \
    const int li   = lane & 7;                                                  \
    const int seg  = lane >> 3;                                                 \
    int aoff[4], boff[2];                                                       \
    _Pragma("unroll")                                                           \
    for (int mt = 0; mt < 4; mt++)                                              \
        aoff[mt] = (wM + mt*16 + li + (seg & 1)*8) * LDH + (seg >> 1)*8;        \
    _Pragma("unroll")                                                           \
    for (int np = 0; np < 2; np++)                                              \
        boff[np] = (wN + np*16 + li + (seg >> 1)*8) * LDH + (seg & 1)*8;        \
    float acc[4][4][4];                                                         \
    _Pragma("unroll")                                                           \
    for (int i = 0; i < 4; i++)                                                 \
        _Pragma("unroll")                                                       \
        for (int j = 0; j < 4; j++)                                             \
            _Pragma("unroll")                                                   \
            for (int l = 0; l < 4; l++) acc[i][j][l] = 0.f;

#define LOAD_STAGE(s, k0, GA, GB)                                               \
    {                                                                           \
        const int c0 = tid, c1 = tid + 256;                                     \
        cp16h(&As[s][(c0>>2)*LDH + (c0&3)*8],                                   \
              &GA[(size_t)(mB + (c0>>2))*CDIM + (k0) + (c0&3)*8]);              \
        cp16h(&Bs[s][(c0>>2)*LDH + (c0&3)*8],                                   \
              &GB[(size_t)(jB + (c0>>2))*CDIM + (k0) + (c0&3)*8]);              \
        cp16h(&As[s][(c1>>2)*LDH + (c1&3)*8],                                   \
              &GA[(size_t)(mB + (c1>>2))*CDIM + (k0) + (c1&3)*8]);              \
        cp16h(&Bs[s][(c1>>2)*LDH + (c1&3)*8],                                   \
              &GB[(size_t)(jB + (c1>>2))*CDIM + (k0) + (c1&3)*8]);              \
        CP_COMMIT;                                                              \
    }

// 12 iterations; stage s = iter mod 3; prefetch depth 2.
#define GEMM_MAINLOOP(GA, GB)                                                   \
    LOAD_STAGE(0, 0, GA, GB);                                                   \
    LOAD_STAGE(1, BK, GA, GB);                                                  \
    int s = 0;                                                                  \
    for (int k0 = 0; k0 < CDIM; k0 += BK) {                                     \
        if (k0 + BK < CDIM) CP_WAIT(1); else CP_WAIT(0);                        \
        __syncthreads();                                                        \
        if (k0 + 2*BK < CDIM) {                                                 \
            const int sn = (s + 2 >= 3) ? s - 1 : s + 2;                        \
            LOAD_STAGE(sn, k0 + 2*BK, GA, GB);                                  \
        }                                                                       \
        const unsigned uA = (unsigned)__cvta_generic_to_shared(As[s]);          \
        const unsigned uB = (unsigned)__cvta_generic_to_shared(Bs[s]);          \
        _Pragma("unroll")                                                       \
        for (int ks = 0; ks < BK; ks += 16) {                                   \
            unsigned a[4][4], bb[2][4];                                         \
            _Pragma("unroll")                                                   \
            for (int mt = 0; mt < 4; mt++)                                      \
                ldsm_x4(a[mt], uA + 2u * (unsigned)(aoff[mt] + ks));            \
            _Pragma("unroll")                                                   \
            for (int np = 0; np < 2; np++)                                      \
                ldsm_x4(bb[np], uB + 2u * (unsigned)(boff[np] + ks));           \
            _Pragma("unroll")                                                   \
            for (int mt = 0; mt < 4; mt++)                                      \
                _Pragma("unroll")                                               \
                for (int nt = 0; nt < 4; nt++)                                  \
                    mma_f16(acc[mt][nt], a[mt], &bb[nt >> 1][(nt & 1) * 2]);    \
        }                                                                       \
        __syncthreads();                                                        \
        s = (s + 1 >= 3) ? 0 : s + 1;                                           \
    }

// ---------------------------------------------------------------------------
// Kernel 1: qkv GEMM (M=65536, Nout=1152, K=384) + fused epilogue.
// ---------------------------------------------------------------------------
__global__ __launch_bounds__(256) void qkv_gemm(const float* __restrict__ pos)
{
    GEMM_PROLOGUE(g_xh, g_wqkv)
    GEMM_MAINLOOP(g_xh, g_wqkv)

    const int part = jB / CDIM;                 // 0=q, 1=k, 2=v (uniform/block)
#pragma unroll
    for (int mt = 0; mt < 4; mt++) {
#pragma unroll
        for (int nt = 0; nt < 4; nt++) {
            const int j = jB + wN + nt * 8 + 2 * t;
            const int c = j - part * CDIM;
            const int h = c >> 5;
            const int d = c & 31;
#pragma unroll
            for (int hh = 0; hh < 2; hh++) {
                const int m = mB + wM + mt * 16 + g + hh * 8;
                const int b_ = m >> 12;
                const int n  = m & 4095;
                float v0 = acc[mt][nt][hh * 2 + 0];
                float v1 = acc[mt][nt][hh * 2 + 1];
                const size_t o = (((size_t)(b_ * HEADS + h)) * NTOK + n) * HD + d;
                if (part == 0) {
                    *(__half2*)&g_qh[o] =
                        __floats2half2_rn(fmaxf(v0, 0.f), fmaxf(v1, 0.f));
                } else if (part == 1) {
                    v0 = fmaxf(v0 + pos[(size_t)n * CDIM + c],     0.f);
                    v1 = fmaxf(v1 + pos[(size_t)n * CDIM + c + 1], 0.f);
                    *(__half2*)&g_kh[o] = __floats2half2_rn(v0, v1);
                } else {
                    *(__half2*)&g_vh[o] = __floats2half2_rn(v0, v1);
                }
            }
        }
    }
}

// ---------------------------------------------------------------------------
// Kernel 2: kv[bh,c,d] += sum_{chunk} k*v ; ksum fused. grid (192, 8).
// (round-6 version — ncu-confirmed win)
// ---------------------------------------------------------------------------
__global__ __launch_bounds__(256) void kv_kernel()
{
    const int bh  = blockIdx.x;
    const int j0s = blockIdx.y * 512;
    const int tid = threadIdx.x;
    const int g   = tid >> 6;           // row group 0..3
    const int cq  = (tid >> 3) & 7;     // c quad 0..7
    const int dq  = tid & 7;            // d quad 0..7
    const int d32 = tid & 31;
    const int gr8 = tid >> 5;
    __shared__ float sk[64 * 32];
    __shared__ float sv[64 * 32];
    __shared__ float sacc[4][1024];
    __shared__ float sred[256];
    const size_t base = (size_t)bh * NTOK * HD;
    float acc[4][4];
#pragma unroll
    for (int i = 0; i < 4; i++)
#pragma unroll
        for (int j = 0; j < 4; j++) acc[i][j] = 0.f;
    float ksacc = 0.f;

    for (int j0 = j0s; j0 < j0s + 512; j0 += 64) {
        for (int i = tid; i < 512; i += 256) {
            const size_t gi = base + (size_t)j0 * HD + i * 4;
            float2 k01 = __half22float2(*(const __half2*)&g_kh[gi]);
            float2 k23 = __half22float2(*(const __half2*)&g_kh[gi + 2]);
            float2 v01 = __half22float2(*(const __half2*)&g_vh[gi]);
            float2 v23 = __half22float2(*(const __half2*)&g_vh[gi + 2]);
            *(float4*)&sk[i * 4] = make_float4(k01.x, k01.y, k23.x, k23.y);
            *(float4*)&sv[i * 4] = make_float4(v01.x, v01.y, v23.x, v23.y);
        }
        __syncthreads();
#pragma unroll
        for (int rr = 0; rr < 16; rr++) {
            const int r = rr * 4 + g;
            float4 kk = *(const float4*)&sk[r * 32 + cq * 4];
            float4 vv = *(const float4*)&sv[r * 32 + dq * 4];
            acc[0][0] += kk.x * vv.x; acc[0][1] += kk.x * vv.y;
            acc[0][2] += kk.x * vv.z; acc[0][3] += kk.x * vv.w;
            acc[1][0] += kk.y * vv.x; acc[1][1] += kk.y * vv.y;
            acc[1][2] += kk.y * vv.z; acc[1][3] += kk.y * vv.w;
            acc[2][0] += kk.z * vv.x; acc[2][1] += kk.z * vv.y;
            acc[2][2] += kk.z * vv.z; acc[2][3] += kk.z * vv.w;
            acc[3][0] += kk.w * vv.x; acc[3][1] += kk.w * vv.y;
            acc[3][2] += kk.w * vv.z; acc[3][3] += kk.w * vv.w;
        }
#pragma unroll
        for (int r8 = 0; r8 < 8; r8++) ksacc += sk[(gr8 + r8 * 8) * 32 + d32];
        __syncthreads();
    }

#pragma unroll
    for (int i = 0; i < 4; i++)
        *(float4*)&sacc[g][(cq * 4 + i) * 32 + dq * 4] =
            make_float4(acc[i][0], acc[i][1], acc[i][2], acc[i][3]);
    sred[tid] = ksacc;
    __syncthreads();
    {
        float4 a0 = *(const float4*)&sacc[0][tid * 4];
        float4 a1 = *(const float4*)&sacc[1][tid * 4];
        float4 a2 = *(const float4*)&sacc[2][tid * 4];
        float4 a3 = *(const float4*)&sacc[3][tid * 4];
        atomicAdd(&g_kv[bh * 1024 + tid * 4 + 0], a0.x + a1.x + a2.x + a3.x);
        atomicAdd(&g_kv[bh * 1024 + tid * 4 + 1], a0.y + a1.y + a2.y + a3.y);
        atomicAdd(&g_kv[bh * 1024 + tid * 4 + 2], a0.z + a1.z + a2.z + a3.z);
        atomicAdd(&g_kv[bh * 1024 + tid * 4 + 3], a0.w + a1.w + a2.w + a3.w);
    }
    if (gr8 == 0) {
        float ssum = 0.f;
#pragma unroll
        for (int gg = 0; gg < 8; gg++) ssum += sred[gg * 32 + d32];
        atomicAdd(&g_ksum[bh * HD + d32], ssum);
    }
}

// ---------------------------------------------------------------------------
// Kernel 4: attn_out (unchanged).
// ---------------------------------------------------------------------------
#define SV_ROW (68 * 32)
#define ATTN_SMEM (5*SV_ROW*2 + (2048 + 1024 + 800 + 32) * 4)

__global__ __launch_bounds__(256, 4) void attn_out(const float* __restrict__ dwc_w,
                                                   const float* __restrict__ dwc_b)
{
    extern __shared__ float sm[];
    __half* svh = (__half*)sm;                  // 5 * SV_ROW halfs
    float* sq  = sm + (5 * SV_ROW * 2) / 4;     // 2048 floats
    float* skv = sq + 2048;                     // 1024
    float* sw  = skv + 1024;                    // 800
    float* sks = sw + 800;                      // 32

    const int y  = blockIdx.x;
    const int bh = blockIdx.y;
    const int tid = threadIdx.x;
    const int d  = tid & 31;
    const int gr = tid >> 5;
    const int x0 = gr * 8;
    const size_t base = (size_t)bh * NTOK * HD;

    for (int i = tid; i < 5 * 4 * 32; i += 256) {
        const int row = i >> 7;
        const int rem = i & 127;
        const int col = rem >> 5;
        const int dd  = rem & 31;
        const int xc  = (col < 2) ? col : (64 + col);
        svh[row * SV_ROW + xc * 32 + dd] = __float2half(0.f);
    }
#pragma unroll
    for (int ky = 0; ky < 5; ky++) {
        const int yy = y + ky - 2;
        for (int c = tid; c < 512; c += 256) {
            const int x = c >> 3, dq = (c & 7) * 4;
            uint2 val = make_uint2(0u, 0u);
            if ((unsigned)yy < 64u)
                val = *(const uint2*)&g_vh[base + ((size_t)(yy * 64 + x)) * HD + dq];
            *(uint2*)&svh[ky * SV_ROW + (x + 2) * 32 + dq] = val;
        }
    }
    for (int c = tid; c < 512; c += 256) {
        const int x = c >> 3, dq = (c & 7) * 4;
        const size_t gi = base + ((size_t)(y * 64 + x)) * HD + dq;
        float2 a = __half22float2(*(const __half2*)&g_qh[gi]);
        float2 bq = __half22float2(*(const __half2*)&g_qh[gi + 2]);
        *(float4*)&sq[x * 32 + dq] = make_float4(a.x, a.y, bq.x, bq.y);
    }
    *(float4*)&skv[tid * 4] = *(const float4*)&g_kv[bh * 1024 + tid * 4];
    for (int i = tid; i < 800; i += 256) sw[i] = dwc_w[i];
    if (tid < 32) sks[tid] = g_ksum[bh * HD + tid];
    __syncthreads();

    float rkv[32];
#pragma unroll
    for (int c = 0; c < 32; c++) rkv[c] = skv[c * 32 + d];
    const float rks = sks[d];
    const float rb  = dwc_b[d];

    float acc[8];
#pragma unroll
    for (int xi = 0; xi < 8; xi++) acc[xi] = rb;
#pragma unroll
    for (int ky = 0; ky < 5; ky++) {
        float w[12];
#pragma unroll
        for (int j = 0; j < 12; j++)
            w[j] = __half2float(svh[ky * SV_ROW + (x0 + j) * 32 + d]);
#pragma unroll
        for (int kx = 0; kx < 5; kx++) {
            const float cf = sw[d * 25 + ky * 5 + kx];
#pragma unroll
            for (int xi = 0; xi < 8; xi++) acc[xi] += cf * w[xi + kx];
        }
    }

    const int b_ = bh / HEADS, h = bh % HEADS;
#pragma unroll
    for (int xi = 0; xi < 8; xi++) {
        const int tok = x0 + xi;
        float o = 0.f;
#pragma unroll
        for (int c = 0; c < 32; c++) o += sq[tok * 32 + c] * rkv[c];
        float p = sq[tok * 32 + d] * rks;
#pragma unroll
        for (int off = 16; off; off >>= 1) p += __shfl_xor_sync(0xffffffffu, p, off);
        const float z = 1.f / (p + EPS);
        const int n = y * 64 + tok;
        g_preh[((size_t)(b_ * NTOK + n)) * CDIM + h * HD + d] =
            __float2half_rn(o * z + acc[xi]);
    }
}

// ---------------------------------------------------------------------------
// Kernel 5: proj GEMM (M=65536, Nout=384, K=384) + bias -> out (fp32).
// ---------------------------------------------------------------------------
__global__ __launch_bounds__(256) void proj_gemm(const float* __restrict__ bias,
                                                 float* __restrict__ out)
{
    GEMM_PROLOGUE(g_preh, g_wproj)
    GEMM_MAINLOOP(g_preh, g_wproj)

#pragma unroll
    for (int mt = 0; mt < 4; mt++) {
#pragma unroll
        for (int nt = 0; nt < 4; nt++) {
            const int j = jB + wN + nt * 8 + 2 * t;
            const float b0 = bias[j], b1 = bias[j + 1];
#pragma unroll
            for (int hh = 0; hh < 2; hh++) {
                const int m = mB + wM + mt * 16 + g + hh * 8;
                *(float2*)&out[(size_t)m * CDIM + j] =
                    make_float2(acc[mt][nt][hh * 2 + 0] + b0,
                                acc[mt][nt][hh * 2 + 1] + b1);
            }
        }
    }
}

// ---------------------------------------------------------------------------
extern "C" void kernel_launch(void* const* d_in, const int* in_sizes, int n_in,
                              void* d_out, int out_size)
{
    const float* x      = (const float*)d_in[0];
    const float* qkv_w  = (const float*)d_in[1];
    const float* pos    = (const float*)d_in[2];
    const float* dwc_w  = (const float*)d_in[3];
    const float* dwc_b  = (const float*)d_in[4];
    const float* proj_w = (const float*)d_in[5];
    const float* proj_b = (const float*)d_in[6];
    float* out = (float*)d_out;

    cudaFuncSetAttribute(qkv_gemm,  cudaFuncAttributeMaxDynamicSharedMemorySize, GEMM_SMEM);
    cudaFuncSetAttribute(proj_gemm, cudaFuncAttributeMaxDynamicSharedMemorySize, GEMM_SMEM);
    cudaFuncSetAttribute(attn_out,  cudaFuncAttributeMaxDynamicSharedMemorySize, ATTN_SMEM);

    cvt_x<<<24576, 256>>>((const float4*)x);
    cvt_w_zero<<<2304, 256>>>(qkv_w, proj_w);

    dim3 g1(9, M_TOT / 128);              // 1152/128 x 512
    qkv_gemm<<<g1, 256, GEMM_SMEM>>>(pos);

    dim3 g3(BH_TOT, 8);
    kv_kernel<<<g3, 256>>>();

    dim3 g4(64, BH_TOT);
    attn_out<<<g4, 256, ATTN_SMEM>>>(dwc_w, dwc_b);

    dim3 g5(3, M_TOT / 128);              // 384/128 x 512
    proj_gemm<<<g5, 256, GEMM_SMEM>>>(proj_b, out);
}